// round 4
// baseline (speedup 1.0000x reference)
#include <cuda_runtime.h>

typedef unsigned long long u64;

#define HW    64
#define F     64
#define D     75
#define CCH   3
#define KR    5
#define TW    32          // wo per CTA
#define SXW   36          // TW + 4 halo
#define NTHR  128

// shared layout (u64 units)
#define OFF_WP  0                   // weights pairs: [75][32] u64  = 2400
#define OFF_XP  2400                // patch dup:   [3][5][36] u64  = 540
#define OFF_X2  2940                // x2: 32 floats = 16 u64
#define OFF_W2  2956                // w2 pairs: 32 u64
#define SMEM_U64 2988
// sout aliases OFF_WP (1024 u64 = 2048 floats)

__global__ __launch_bounds__(NTHR, 7)
void euclid2d_kernel(const float* __restrict__ x,
                     const float* __restrict__ W,
                     float* __restrict__ out) {
    __shared__ __align__(16) u64 S[SMEM_U64];
    float* Sf = (float*)S;

    const int tid  = threadIdx.x;
    const int lane = tid & 31;
    const int w    = tid >> 5;          // warp 0..3
    const int bx   = blockIdx.x;        // 0..1 (wo tile)
    const int ho   = blockIdx.y;        // 0..63
    const int n    = blockIdx.z;        // 0..7

    // ---- fill weight pairs: pair at [d][fp] = (W[2fp][d], W[2fp+1][d]) ----
    for (int i = tid; i < F * D; i += NTHR) {
        int f = i / D, d = i % D;
        Sf[(OFF_WP + d * 32 + (f >> 1)) * 2 + (f & 1)] = W[i];
    }

    // ---- fill patch tile, duplicated (v,v); col maps to gx = x0 + col ----
    const int x0 = bx * TW - 2;
    const int y0 = ho - 2;
    for (int i = tid; i < CCH * KR * SXW; i += NTHR) {
        int c   = i / (KR * SXW);
        int r   = (i / SXW) % KR;
        int col = i % SXW;
        int gy = y0 + r, gx = x0 + col;
        float v = 0.0f;
        if (gy >= 0 && gy < HW && gx >= 0 && gx < HW)
            v = x[((n * CCH + c) * HW + gy) * HW + gx];
        u64 p;
        asm("mov.b64 %0, {%1, %1};" : "=l"(p) : "f"(v));
        S[OFF_XP + i] = p;
    }
    __syncthreads();

    // ---- x2 per pixel (4 threads/pixel, stride-4 partials + shfl) ----
    {
        const int p = tid >> 2;     // CTA pixel 0..31
        const int q = tid & 3;
        float s = 0.0f;
        #pragma unroll
        for (int k = 0; k < 19; k++) {
            int j = q + 4 * k;
            if (j < D) {
                int c = j / 25, kh = (j % 25) / 5, kw = j % 5;
                float v = Sf[(OFF_XP + (c * 5 + kh) * 36 + p + kw) * 2];
                s += v * v;
            }
        }
        s += __shfl_xor_sync(0xffffffffu, s, 1);
        s += __shfl_xor_sync(0xffffffffu, s, 2);
        if (q == 0) Sf[OFF_X2 * 2 + p] = s;
    }
    // ---- w2 per filter-pair (warp 0 only) ----
    if (tid < 32) {
        u64 w2 = 0ULL;
        #pragma unroll
        for (int d = 0; d < D; d++) {
            u64 wv = S[OFF_WP + d * 32 + tid];
            asm("fma.rn.f32x2 %0, %1, %1, %0;" : "+l"(w2) : "l"(wv));
        }
        S[OFF_W2 + tid] = w2;
    }
    __syncthreads();

    // ---- main loop: lane = filter pair, thread = 8 pixels ----
    u64 acc[8];
    #pragma unroll
    for (int p = 0; p < 8; p++) acc[p] = 0ULL;

    #pragma unroll
    for (int c = 0; c < CCH; c++)
        #pragma unroll
        for (int kh = 0; kh < KR; kh++) {
            const int row = c * 5 + kh;
            // pixels w*8 .. w*8+7 with kw 0..4 need patch cols w*8 .. w*8+11
            const ulonglong2* prow =
                (const ulonglong2*)&S[OFF_XP + row * 36 + w * 8];
            ulonglong2 P2[6];
            #pragma unroll
            for (int t = 0; t < 6; t++) P2[t] = prow[t];   // LDS.128 broadcast
            const u64* Pu = (const u64*)P2;                 // 12 u64 in regs
            #pragma unroll
            for (int kw = 0; kw < KR; kw++) {
                u64 wv = S[OFF_WP + (row * 5 + kw) * 32 + lane];  // LDS.64 contiguous
                #pragma unroll
                for (int p = 0; p < 8; p++)
                    asm("fma.rn.f32x2 %0, %1, %2, %0;"
                        : "+l"(acc[p]) : "l"(Pu[kw + p]), "l"(wv));
            }
        }

    // ---- epilogue: res = acc - 0.5*(x2 + w2) ----
    u64 w2l = S[OFF_W2 + lane];
    u64 nh;
    { float mh = -0.5f; asm("mov.b64 %0, {%1, %1};" : "=l"(nh) : "f"(mh)); }

    u64 res[8];
    #pragma unroll
    for (int p = 0; p < 8; p++) {
        float x2 = Sf[OFF_X2 * 2 + w * 8 + p];
        u64 x2d;
        asm("mov.b64 %0, {%1, %1};" : "=l"(x2d) : "f"(x2));
        u64 s;
        asm("add.rn.f32x2 %0, %1, %2;" : "=l"(s) : "l"(x2d), "l"(w2l));
        u64 r = acc[p];
        asm("fma.rn.f32x2 %0, %1, %2, %0;" : "+l"(r) : "l"(s), "l"(nh));
        res[p] = r;
    }

    __syncthreads();   // all weight reads done before aliasing sout over OFF_WP

    // sout[pix][fpair]: u64 at [pix*32 + lane]
    #pragma unroll
    for (int p = 0; p < 8; p++)
        S[(w * 8 + p) * 32 + lane] = res[p];
    __syncthreads();

    // write: thread -> filter f = tid>>1, half = tid&1 (16 consecutive wo)
    {
        const int f    = tid >> 1;
        const int half = tid & 1;
        float v[16];
        #pragma unroll
        for (int j = 0; j < 16; j++)
            v[j] = Sf[(half * 16 + j) * 64 + f];
        float* op = out + (((long)(n * F + f) * HW + ho) * HW) + bx * TW + half * 16;
        #pragma unroll
        for (int j = 0; j < 4; j++) {
            float4 q4 = make_float4(v[4*j], v[4*j+1], v[4*j+2], v[4*j+3]);
            *(float4*)(op + 4 * j) = q4;
        }
    }
}

extern "C" void kernel_launch(void* const* d_in, const int* in_sizes, int n_in,
                              void* d_out, int out_size) {
    const float* x = (const float*)d_in[0];
    const float* W = (const float*)d_in[1];
    float* out = (float*)d_out;

    dim3 grid(HW / TW, HW, 8);   // (2, 64, 8) = 1024 CTAs
    euclid2d_kernel<<<grid, NTHR>>>(x, W, out);
}

// round 5
// speedup vs baseline: 1.4863x; 1.4863x over previous
#include <cuda_runtime.h>

typedef unsigned long long u64;

#define HW   64
#define F    64
#define D    75
#define KR   5
#define SXW  68          // 64 + 4 halo
#define NROW 15          // 3 channels * 5 kernel rows
#define NTHR 256

// shared layout (u64 units)
#define OFF_WP  0        // weight pairs [75][32] u64            = 2400
#define OFF_XP  2400     // patch dup    [15][68] u64            = 1020
#define OFF_X2  3420     // x2: 64 floats                        = 32
#define OFF_W2  3452     // w2 pairs: 32 u64                     = 32
#define OFF_SW  3484     // w2 partials: [4][32] u64             = 128
#define OFF_SX  3612     // x2 partials: [4][64] f32             = 128
#define SMEM_U64 3740    // 29920 B

__global__ __launch_bounds__(NTHR, 4)
void euclid2d_kernel(const float* __restrict__ x,
                     const float* __restrict__ W,
                     float* __restrict__ out) {
    __shared__ __align__(16) u64 S[SMEM_U64];
    float* Sf = (float*)S;

    const int tid  = threadIdx.x;
    const int lane = tid & 31;
    const int w    = tid >> 5;          // warp 0..7 -> pixels w*8..w*8+7
    const int ho   = blockIdx.x;        // 0..63
    const int n    = blockIdx.y;        // 0..7

    // ---- weight pairs: dest-ordered (conflict-free STS.64), gathered LDG ----
    #pragma unroll
    for (int k = 0; k < 10; k++) {
        int j = tid + k * NTHR;          // u64 index: d*32 + fp
        if (j < 2400) {
            int d  = j >> 5;
            int fp = j & 31;
            float lo = W[(2 * fp)     * D + d];
            float hi = W[(2 * fp + 1) * D + d];
            u64 p;
            asm("mov.b64 %0, {%1, %2};" : "=l"(p) : "f"(lo), "f"(hi));
            S[OFF_WP + j] = p;
        }
    }

    // ---- patch tile (duplicated pairs), rows = c*5+kh ----
    const int y0 = ho - 2;
    #pragma unroll
    for (int k = 0; k < 4; k++) {
        int i = tid + k * NTHR;          // 0..1019
        if (i < NROW * SXW) {
            int row = i / SXW;           // 0..14
            int col = i % SXW;
            int c  = row / KR;
            int kh = row % KR;
            int gy = y0 + kh;
            int gx = col - 2;
            float v = 0.0f;
            if (gy >= 0 && gy < HW && gx >= 0 && gx < HW)
                v = x[((n * 3 + c) * HW + gy) * HW + gx];
            u64 p;
            asm("mov.b64 %0, {%1, %1};" : "=l"(p) : "f"(v));
            S[OFF_XP + i] = p;
        }
    }
    __syncthreads();

    // ---- partial sums: w2 (tid<128) and x2 (all threads), 4-way d-split ----
    if (tid < 128) {
        int fp = tid & 31, q = tid >> 5;
        u64 a = 0ULL;
        for (int d = q; d < D; d += 4) {
            u64 wv = S[OFF_WP + d * 32 + fp];
            asm("fma.rn.f32x2 %0, %1, %1, %0;" : "+l"(a) : "l"(wv));
        }
        S[OFF_SW + q * 32 + fp] = a;
    }
    {
        int p = tid & 63, q = tid >> 6;
        float s = 0.0f;
        for (int d = q; d < D; d += 4) {
            int row = d / KR, kw = d % KR;
            float v = Sf[(OFF_XP + row * SXW + p + kw) * 2];
            s += v * v;
        }
        Sf[(OFF_SX) * 2 + q * 64 + p] = s;
    }
    __syncthreads();

    if (tid < 32) {                      // reduce w2
        u64 a = S[OFF_SW + tid], b = S[OFF_SW + 32 + tid];
        u64 c = S[OFF_SW + 64 + tid], dd = S[OFF_SW + 96 + tid];
        u64 r;
        asm("add.rn.f32x2 %0, %1, %2;" : "=l"(r) : "l"(a), "l"(b));
        asm("add.rn.f32x2 %0, %0, %1;" : "+l"(r) : "l"(c));
        asm("add.rn.f32x2 %0, %0, %1;" : "+l"(r) : "l"(dd));
        S[OFF_W2 + tid] = r;
    } else if (tid >= 64 && tid < 128) { // reduce x2
        int p = tid - 64;
        float r = Sf[OFF_SX * 2 + p] + Sf[OFF_SX * 2 + 64 + p]
                + Sf[OFF_SX * 2 + 128 + p] + Sf[OFF_SX * 2 + 192 + p];
        Sf[OFF_X2 * 2 + p] = r;
    }
    __syncthreads();

    // ---- main loop: lane = filter pair, thread = 8 pixels ----
    u64 acc[8];
    #pragma unroll
    for (int p = 0; p < 8; p++) acc[p] = 0ULL;

    #pragma unroll
    for (int row = 0; row < NROW; row++) {
        const ulonglong2* prow =
            (const ulonglong2*)&S[OFF_XP + row * SXW + w * 8];
        ulonglong2 P2[6];
        #pragma unroll
        for (int t = 0; t < 6; t++) P2[t] = prow[t];       // LDS.128 broadcast
        const u64* Pu = (const u64*)P2;
        #pragma unroll
        for (int kw = 0; kw < KR; kw++) {
            u64 wv = S[OFF_WP + (row * KR + kw) * 32 + lane];   // LDS.64
            #pragma unroll
            for (int p = 0; p < 8; p++)
                asm("fma.rn.f32x2 %0, %1, %2, %0;"
                    : "+l"(acc[p]) : "l"(Pu[kw + p]), "l"(wv));
        }
    }

    // ---- epilogue: res = acc - 0.5*(x2+w2); direct 32B-sector STG ----
    u64 w2l = S[OFF_W2 + lane];
    u64 nh;
    { float mh = -0.5f; asm("mov.b64 %0, {%1, %1};" : "=l"(nh) : "f"(mh)); }

    float lo[8], hi[8];
    #pragma unroll
    for (int p = 0; p < 8; p++) {
        float x2 = Sf[OFF_X2 * 2 + w * 8 + p];
        u64 x2d, s, r = acc[p];
        asm("mov.b64 %0, {%1, %1};" : "=l"(x2d) : "f"(x2));
        asm("add.rn.f32x2 %0, %1, %2;" : "=l"(s) : "l"(x2d), "l"(w2l));
        asm("fma.rn.f32x2 %0, %1, %2, %0;" : "+l"(r) : "l"(s), "l"(nh));
        asm("mov.b64 {%0, %1}, %2;" : "=f"(lo[p]), "=f"(hi[p]) : "l"(r));
    }

    const int f0 = 2 * lane;
    float* op0 = out + (((long)(n * F + f0)     * HW + ho) * HW) + w * 8;
    float* op1 = op0 + (long)HW * HW;   // filter f0+1

    *(float4*)(op0)     = make_float4(lo[0], lo[1], lo[2], lo[3]);
    *(float4*)(op0 + 4) = make_float4(lo[4], lo[5], lo[6], lo[7]);
    *(float4*)(op1)     = make_float4(hi[0], hi[1], hi[2], hi[3]);
    *(float4*)(op1 + 4) = make_float4(hi[4], hi[5], hi[6], hi[7]);
}

extern "C" void kernel_launch(void* const* d_in, const int* in_sizes, int n_in,
                              void* d_out, int out_size) {
    const float* x = (const float*)d_in[0];
    const float* W = (const float*)d_in[1];
    float* out = (float*)d_out;

    dim3 grid(HW, 8);    // (ho, n) = 512 CTAs
    euclid2d_kernel<<<grid, NTHR>>>(x, W, out);
}